// round 16
// baseline (speedup 1.0000x reference)
#include <cuda_runtime.h>

// Sinkhorn OT loss on 64x64 pooled grids. K = exp(-C/0.1) is exact (to fp32)
// as two 3-tap separable passes, W1 = exp(-10).
// R16: TEMPORAL BLOCKING. Same CTA window as R10/R15 (8 owned + 4+4 zero-halo,
// 8 blocks/batch, 128 thr / 4 warps, lane = 2 cols), but each warp holds a
// 12-row register window (its 4 window-rows +-4) and runs FOUR halfsteps per
// exchange with shrinking valid ranges 10->8->6->4 -- bit-exact by stencil
// locality. One STS/BAR/LDS exchange per 4 halfsteps instead of per halfstep:
// the ~230-cyc barrier chain that bound R4-R15 is amortized 4x.

#define NBATCH 16
#define EPS    1e-8f
#define W1     4.5399929762484854e-05f   // exp(-10)

__device__ float g_pooled[2][NBATCH][4096];
__device__ float g_psum[2][NBATCH][16];    // per pool-block partial sums
__device__ float g_costs[NBATCH * 8];      // [batch*8 + block]
__device__ int   g_done;

// ---------------------------------------------------------------- pooling
__global__ __launch_bounds__(256) void pool_kernel(const float* __restrict__ pred,
                                                   const float* __restrict__ gt) {
    __shared__ float red[8];
    const int bid    = blockIdx.x;          // 0..511
    const int tensor = bid >> 8;
    const int batch  = (bid >> 4) & 15;
    const int rb     = bid & 15;            // block of 4 pooled rows
    const float* src = (tensor ? gt : pred) + (size_t)batch * 262144;

    const int pr = rb * 4 + (threadIdx.x >> 6);
    const int pc = threadIdx.x & 63;
    const float4* p = (const float4*)(src + (size_t)pr * 4096 + pc * 8);

    float s = 0.f;
#pragma unroll
    for (int y = 0; y < 8; ++y) {
        float4 v0 = p[y * 128];
        float4 v1 = p[y * 128 + 1];
        s += (v0.x + v0.y) + (v0.z + v0.w) + (v1.x + v1.y) + (v1.z + v1.w);
    }
    g_pooled[tensor][batch][pr * 64 + pc] = s;

    float v = s;
#pragma unroll
    for (int o = 16; o; o >>= 1) v += __shfl_xor_sync(0xffffffffu, v, o);
    const int w = threadIdx.x >> 5, l = threadIdx.x & 31;
    if (l == 0) red[w] = v;
    __syncthreads();
    if (threadIdx.x == 0) {
        float tot = ((red[0] + red[1]) + (red[2] + red[3]))
                  + ((red[4] + red[5]) + (red[6] + red[7]));
        g_psum[tensor][batch][rb] = tot;
    }
}

// ---------------------------------------------------------------- sinkhorn
// One halfstep on register rows: o[r] = tg[r] / (Ve(He(in))[r] + eps) for
// r in [LO, HI]; consumes in[LO-1 .. HI+1] (all valid by construction).
template<int LO, int HI>
__device__ __forceinline__ void halfstep(float2* o, const float2* tg,
                                         const float2* in, const int l) {
    float2 H[HI - LO + 3];   // rows LO-1 .. HI+1
#pragma unroll
    for (int r = LO - 1; r <= HI + 1; ++r) {
        float lf = __shfl_up_sync(0xffffffffu, in[r].y, 1);    // col c0-1
        float rt = __shfl_down_sync(0xffffffffu, in[r].x, 1);  // col c0+2
        if (l == 0)  lf = 0.f;
        if (l == 31) rt = 0.f;
        H[r - LO + 1].x = fmaf(W1, lf + in[r].y, in[r].x);
        H[r - LO + 1].y = fmaf(W1, in[r].x + rt, in[r].y);
    }
#pragma unroll
    for (int r = LO; r <= HI; ++r) {
        const float2 hu = H[r - LO], hc = H[r - LO + 1], hd = H[r - LO + 2];
        o[r].x = __fdividef(tg[r].x, fmaf(W1, hu.x + hd.x, hc.x + EPS));
        o[r].y = __fdividef(tg[r].y, fmaf(W1, hu.y + hd.y, hc.y + EPS));
    }
}

__global__ __launch_bounds__(128, 1) void sinkhorn_kernel(float* __restrict__ out) {
    // exchange buffer: [parity][warp-slot][4 rows][64 cols]; slots 0,5 = zeros
    __shared__ __align__(8) float SX[2][6][4][64];
    __shared__ float red[4];

    const int t     = threadIdx.x;          // 0..127
    const int w     = t >> 5;               // warp = 4 window-rows
    const int l     = t & 31;
    const int c0    = 2 * l;                // lane's columns c0, c0+1
    const int q     = blockIdx.x & 7;       // row-block within batch
    const int batch = blockIdx.x >> 3;

    // zero the permanent halo slots (both parities)
    for (int i = t; i < 4 * 64; i += 128) {
        const int rr = i >> 6, cc = i & 63;
        SX[0][0][rr][cc] = 0.f; SX[0][5][rr][cc] = 0.f;
        SX[1][0][rr][cc] = 0.f; SX[1][5][rr][cc] = 0.f;
    }

    // ---- batch-wide sums from pool partials (fixed linear order) ----
    float asum = 0.f, bsum = 0.f;
#pragma unroll
    for (int i = 0; i < 16; ++i) {
        asum += g_psum[0][batch][i];
        bsum += g_psum[1][batch][i];
    }
    const float ra  = 1.f / fmaxf(asum, 1e-8f);
    const float rbv = 1.f / fmaxf(bsum, 1e-8f);

    // ---- 12-row register window per warp ----
    // register row r (0..11) <-> CTA-window row wr = 4w-4+r <-> grid row
    // G = 8q-4+wr. Fields are nonzero only inside BOTH the CTA window (0..15)
    // and the grid (0..63): identical zero-extension semantics to R10.
    float2 a[12], b[12], u[12], v[12];
#pragma unroll
    for (int r = 0; r < 12; ++r) {
        const int wr = 4 * w - 4 + r;
        const int G  = 8 * q - 4 + wr;
        if (wr >= 0 && wr < 16 && G >= 0 && G < 64) {
            const float2 x = *(const float2*)&g_pooled[0][batch][G * 64 + c0];
            const float2 y = *(const float2*)&g_pooled[1][batch][G * 64 + c0];
            a[r] = make_float2(x.x * ra,  x.y * ra);
            b[r] = make_float2(y.x * rbv, y.y * rbv);
            u[r] = make_float2(1.f, 1.f);
        } else {
            a[r] = make_float2(0.f, 0.f);
            b[r] = make_float2(0.f, 0.f);
            u[r] = make_float2(0.f, 0.f);
        }
        v[r] = make_float2(0.f, 0.f);
    }
    __syncthreads();   // zero-slot init visible before first exchange reads

    // ---- cycle 0 (u valid on all 12 rows from init; no exchange) ----
    halfstep<1, 10>(v, b, u, l);   // v valid 1..10
    halfstep<2,  9>(u, a, v, l);   // u valid 2..9
    halfstep<3,  8>(v, b, u, l);   // v valid 3..8
    halfstep<4,  7>(u, a, v, l);   // u valid 4..7 (owned)

    // ---- cycles 1..24: exchange (1 barrier) + 4 halfsteps ----
#pragma unroll 1
    for (int c = 1; c < 25; ++c) {
        const int p = c & 1;
#pragma unroll
        for (int i = 0; i < 4; ++i)
            *(float2*)&SX[p][w + 1][i][c0] = u[4 + i];
        __syncthreads();
#pragma unroll
        for (int i = 0; i < 4; ++i) {
            u[i]     = *(const float2*)&SX[p][w][i][c0];      // above neighbor
            u[8 + i] = *(const float2*)&SX[p][w + 2][i][c0];  // below neighbor
        }
        halfstep<1, 10>(v, b, u, l);
        halfstep<2,  9>(u, a, v, l);
        halfstep<3,  8>(v, b, u, l);
        halfstep<4,  7>(u, a, v, l);
    }
    // final state: v valid rows 3..8, u valid rows 4..7 -- exactly what the
    // cost stencil needs; NO final exchange required.

    // ---- cost on owned rows 4..7: u.(Mv),
    //      Mv = Hg(v) + W1*(T[r-1]+T[r+1]), T = v + 2*Hg(v) ----
    float2 HG[6], T[6];   // rows 3..8
#pragma unroll
    for (int k = 0; k < 6; ++k) {
        const int r = 3 + k;
        float lf = __shfl_up_sync(0xffffffffu, v[r].y, 1);
        float rt = __shfl_down_sync(0xffffffffu, v[r].x, 1);
        if (l == 0)  lf = 0.f;
        if (l == 31) rt = 0.f;
        HG[k].x = W1 * (lf + v[r].y);
        HG[k].y = W1 * (v[r].x + rt);
        T[k].x  = fmaf(2.f, HG[k].x, v[r].x);
        T[k].y  = fmaf(2.f, HG[k].y, v[r].y);
    }
    float local = 0.f;
#pragma unroll
    for (int k = 1; k <= 4; ++k) {        // rows r = 4..7
        const float mvx = fmaf(W1, T[k - 1].x + T[k + 1].x, HG[k].x);
        const float mvy = fmaf(W1, T[k - 1].y + T[k + 1].y, HG[k].y);
        local = fmaf(u[3 + k].x, mvx, fmaf(u[3 + k].y, mvy, local));
    }
    // only warps 1,2 hold CTA-owned rows (w0/w3 hold the CTA halo)
    local = ((w == 1) || (w == 2)) ? local : 0.f;

#pragma unroll
    for (int o = 16; o; o >>= 1) local += __shfl_xor_sync(0xffffffffu, local, o);
    if (l == 0) red[w] = local;
    __syncthreads();

    if (t == 0) {
        g_costs[blockIdx.x] = (red[0] + red[1]) + (red[2] + red[3]);
        __threadfence();
        const int prev = atomicAdd(&g_done, 1);
        if (prev == 8 * NBATCH - 1) {
            g_done = 0;
            __threadfence();
            float s = 0.f;
#pragma unroll 1
            for (int bb = 0; bb < NBATCH; ++bb) {
                float as = 0.f, bs = 0.f;
#pragma unroll
                for (int i = 0; i < 16; ++i) {
                    as += g_psum[0][bb][i];
                    bs += g_psum[1][bb][i];
                }
                float cst = 0.f;
#pragma unroll
                for (int k = 0; k < 8; ++k) cst += g_costs[8 * bb + k];
                s += ((as > 0.5f) && (bs > 0.5f)) ? cst : 0.f;
            }
            out[0] = s * (1.f / (float)NBATCH);
        }
    }
}

extern "C" void kernel_launch(void* const* d_in, const int* in_sizes, int n_in,
                              void* d_out, int out_size) {
    (void)in_sizes; (void)n_in; (void)out_size;
    const float* pred = (const float*)d_in[0];
    const float* gt   = (const float*)d_in[1];
    pool_kernel<<<512, 256>>>(pred, gt);
    sinkhorn_kernel<<<NBATCH * 8, 128>>>((float*)d_out);
}

// round 17
// speedup vs baseline: 1.0779x; 1.0779x over previous
#include <cuda_runtime.h>

// Sinkhorn OT loss on 64x64 pooled grids. K = exp(-C/0.1) is exact (to fp32)
// as two 3-tap separable passes, W1 = exp(-10).
// R17: temporal blocking k=2 (R16 was k=4 and SPILLED: 120+ live floats vs 103
// regs). Warp holds an 8-row register window (4 owned +-2) and runs TWO
// halfsteps per STS/BAR/LDS exchange, valid rows 6->4 -- bit-exact to R10 by
// stencil locality. Live state ~52 floats + 16 temp -> ~85 regs, no spill.
// Redundancy 1.25x (vs R16's 1.75x); barrier chain amortized 2x.

#define NBATCH 16
#define EPS    1e-8f
#define W1     4.5399929762484854e-05f   // exp(-10)

__device__ float g_pooled[2][NBATCH][4096];
__device__ float g_psum[2][NBATCH][16];    // per pool-block partial sums
__device__ float g_costs[NBATCH * 8];      // [batch*8 + block]
__device__ int   g_done;

// ---------------------------------------------------------------- pooling
__global__ __launch_bounds__(256) void pool_kernel(const float* __restrict__ pred,
                                                   const float* __restrict__ gt) {
    __shared__ float red[8];
    const int bid    = blockIdx.x;          // 0..511
    const int tensor = bid >> 8;
    const int batch  = (bid >> 4) & 15;
    const int rb     = bid & 15;            // block of 4 pooled rows
    const float* src = (tensor ? gt : pred) + (size_t)batch * 262144;

    const int pr = rb * 4 + (threadIdx.x >> 6);
    const int pc = threadIdx.x & 63;
    const float4* p = (const float4*)(src + (size_t)pr * 4096 + pc * 8);

    float s = 0.f;
#pragma unroll
    for (int y = 0; y < 8; ++y) {
        float4 v0 = p[y * 128];
        float4 v1 = p[y * 128 + 1];
        s += (v0.x + v0.y) + (v0.z + v0.w) + (v1.x + v1.y) + (v1.z + v1.w);
    }
    g_pooled[tensor][batch][pr * 64 + pc] = s;

    float v = s;
#pragma unroll
    for (int o = 16; o; o >>= 1) v += __shfl_xor_sync(0xffffffffu, v, o);
    const int w = threadIdx.x >> 5, l = threadIdx.x & 31;
    if (l == 0) red[w] = v;
    __syncthreads();
    if (threadIdx.x == 0) {
        float tot = ((red[0] + red[1]) + (red[2] + red[3]))
                  + ((red[4] + red[5]) + (red[6] + red[7]));
        g_psum[tensor][batch][rb] = tot;
    }
}

// ---------------------------------------------------------------- sinkhorn
// One halfstep on register rows: o[r] = tg[r] / (Ve(He(in))[r] + eps) for
// r in [LO, HI]; consumes in[LO-1 .. HI+1] (valid by construction).
template<int LO, int HI>
__device__ __forceinline__ void halfstep(float2* o, const float2* tg,
                                         const float2* in, const int l) {
    float2 H[HI - LO + 3];   // rows LO-1 .. HI+1
#pragma unroll
    for (int r = LO - 1; r <= HI + 1; ++r) {
        float lf = __shfl_up_sync(0xffffffffu, in[r].y, 1);    // col c0-1
        float rt = __shfl_down_sync(0xffffffffu, in[r].x, 1);  // col c0+2
        if (l == 0)  lf = 0.f;
        if (l == 31) rt = 0.f;
        H[r - LO + 1].x = fmaf(W1, lf + in[r].y, in[r].x);
        H[r - LO + 1].y = fmaf(W1, in[r].x + rt, in[r].y);
    }
#pragma unroll
    for (int r = LO; r <= HI; ++r) {
        const float2 hu = H[r - LO], hc = H[r - LO + 1], hd = H[r - LO + 2];
        o[r].x = __fdividef(tg[r].x, fmaf(W1, hu.x + hd.x, hc.x + EPS));
        o[r].y = __fdividef(tg[r].y, fmaf(W1, hu.y + hd.y, hc.y + EPS));
    }
}

__global__ __launch_bounds__(128, 1) void sinkhorn_kernel(float* __restrict__ out) {
    // exchange: [parity][slot][owned row 0..3][lane]; slots 0 & 5 stay zero
    __shared__ __align__(8) float2 SX[2][6][4][32];
    __shared__ float red[4];

    const int t     = threadIdx.x;          // 0..127
    const int w     = t >> 5;               // warp = 4 owned window-rows
    const int l     = t & 31;
    const int c0    = 2 * l;                // lane's columns c0, c0+1
    const int q     = blockIdx.x & 7;       // row-block within batch
    const int batch = blockIdx.x >> 3;

    // zero the permanent halo slots (both parities)
    if (t < 64) {
        const int p = t >> 5, rr = (t >> 3) & 3, cc = t & 7;   // cover 2x4x32 via loop
        (void)p; (void)rr; (void)cc;
    }
    for (int i = t; i < 2 * 4 * 32; i += 128) {
        const int p = i >> 7, rr = (i >> 5) & 3, cc = i & 31;
        SX[p][0][rr][cc] = make_float2(0.f, 0.f);
        SX[p][5][rr][cc] = make_float2(0.f, 0.f);
    }

    // ---- batch-wide sums from pool partials (fixed linear order) ----
    float asum = 0.f, bsum = 0.f;
#pragma unroll
    for (int i = 0; i < 16; ++i) {
        asum += g_psum[0][batch][i];
        bsum += g_psum[1][batch][i];
    }
    const float ra  = 1.f / fmaxf(asum, 1e-8f);
    const float rbv = 1.f / fmaxf(bsum, 1e-8f);

    // ---- 8-row register window per warp ----
    // reg row r (0..7) <-> CTA-window row wr = 4w-2+r <-> grid row G = 8q-4+wr.
    // Nonzero only inside window (0..15) AND grid (0..63): R10 semantics.
    float2 a[8], b[8], u[8], v[8];
#pragma unroll
    for (int r = 0; r < 8; ++r) {
        const int wr = 4 * w - 2 + r;
        const int G  = 8 * q - 4 + wr;
        if (wr >= 0 && wr < 16 && G >= 0 && G < 64) {
            const float2 x = *(const float2*)&g_pooled[0][batch][G * 64 + c0];
            const float2 y = *(const float2*)&g_pooled[1][batch][G * 64 + c0];
            a[r] = make_float2(x.x * ra,  x.y * ra);
            b[r] = make_float2(y.x * rbv, y.y * rbv);
            u[r] = make_float2(1.f, 1.f);
        } else {
            a[r] = make_float2(0.f, 0.f);
            b[r] = make_float2(0.f, 0.f);
            u[r] = make_float2(0.f, 0.f);
        }
        v[r] = make_float2(0.f, 0.f);
    }
    __syncthreads();   // zero-slot init visible

    // ---- cycle 0: u valid on all 8 rows from init; no exchange ----
    halfstep<1, 6>(v, b, u, l);   // v valid 1..6
    halfstep<2, 5>(u, a, v, l);   // u valid 2..5 (owned)

    // ---- cycles 1..49: one exchange (1 barrier) + 2 halfsteps ----
#pragma unroll 1
    for (int c = 1; c < 50; ++c) {
        const int p = c & 1;
#pragma unroll
        for (int i = 0; i < 4; ++i)
            SX[p][w + 1][i][l] = u[2 + i];          // my owned rows
        __syncthreads();
        u[0] = SX[p][w][2][l];                      // rows 4w-2, 4w-1
        u[1] = SX[p][w][3][l];
        u[6] = SX[p][w + 2][0][l];                  // rows 4w+4, 4w+5
        u[7] = SX[p][w + 2][1][l];
        halfstep<1, 6>(v, b, u, l);
        halfstep<2, 5>(u, a, v, l);
    }
    // final: v valid 1..6, u valid 2..5 -- exactly what the cost needs.

    // ---- cost on owned rows 2..5: u.(Mv),
    //      Mv = Hg(v) + W1*(T[r-1]+T[r+1]), T = v + 2*Hg(v) ----
    float2 HG[6], T[6];   // rows 1..6
#pragma unroll
    for (int k = 0; k < 6; ++k) {
        const int r = 1 + k;
        float lf = __shfl_up_sync(0xffffffffu, v[r].y, 1);
        float rt = __shfl_down_sync(0xffffffffu, v[r].x, 1);
        if (l == 0)  lf = 0.f;
        if (l == 31) rt = 0.f;
        HG[k].x = W1 * (lf + v[r].y);
        HG[k].y = W1 * (v[r].x + rt);
        T[k].x  = fmaf(2.f, HG[k].x, v[r].x);
        T[k].y  = fmaf(2.f, HG[k].y, v[r].y);
    }
    float local = 0.f;
#pragma unroll
    for (int k = 1; k <= 4; ++k) {        // reg rows 2..5
        const float mvx = fmaf(W1, T[k - 1].x + T[k + 1].x, HG[k].x);
        const float mvy = fmaf(W1, T[k - 1].y + T[k + 1].y, HG[k].y);
        local = fmaf(u[1 + k].x, mvx, fmaf(u[1 + k].y, mvy, local));
    }
    // only warps 1,2 hold CTA-owned rows (w0/w3 hold the CTA halo)
    local = ((w == 1) || (w == 2)) ? local : 0.f;

#pragma unroll
    for (int o = 16; o; o >>= 1) local += __shfl_xor_sync(0xffffffffu, local, o);
    if (l == 0) red[w] = local;
    __syncthreads();

    if (t == 0) {
        g_costs[blockIdx.x] = (red[0] + red[1]) + (red[2] + red[3]);
        __threadfence();
        const int prev = atomicAdd(&g_done, 1);
        if (prev == 8 * NBATCH - 1) {
            g_done = 0;
            __threadfence();
            float s = 0.f;
#pragma unroll 1
            for (int bb = 0; bb < NBATCH; ++bb) {
                float as = 0.f, bs = 0.f;
#pragma unroll
                for (int i = 0; i < 16; ++i) {
                    as += g_psum[0][bb][i];
                    bs += g_psum[1][bb][i];
                }
                float cst = 0.f;
#pragma unroll
                for (int k = 0; k < 8; ++k) cst += g_costs[8 * bb + k];
                s += ((as > 0.5f) && (bs > 0.5f)) ? cst : 0.f;
            }
            out[0] = s * (1.f / (float)NBATCH);
        }
    }
}

extern "C" void kernel_launch(void* const* d_in, const int* in_sizes, int n_in,
                              void* d_out, int out_size) {
    (void)in_sizes; (void)n_in; (void)out_size;
    const float* pred = (const float*)d_in[0];
    const float* gt   = (const float*)d_in[1];
    pool_kernel<<<512, 256>>>(pred, gt);
    sinkhorn_kernel<<<NBATCH * 8, 128>>>((float*)d_out);
}